// round 1
// baseline (speedup 1.0000x reference)
#include <cuda_runtime.h>
#include <cstdint>

// Problem constants
#define BATCH 2
#define SEQ   2048
#define HID   1024
#define NHEAD 16
#define HDIM  64
#define NTOK  (BATCH*SEQ)          // 4096

// Scratch (device globals: allocation-free rule)
__device__ float g_qkv[NTOK * 3 * HID];   // (B,S,3,NH,HD)  ~50 MB
__device__ float g_attn[NTOK * HID];      // (B,S,NH,HD)    ~16 MB

// ---------------------------------------------------------------------------
// SGEMM: C = A(M,K) * B(K,N) + bias(N), all row-major, fp32.
// 128x128 block tile, BK=8, 8x8 per-thread register tile, 256 threads.
// All dims here are multiples of the tile sizes -> no bounds checks.
// ---------------------------------------------------------------------------
__global__ __launch_bounds__(256) void sgemm_bias_kernel(
    const float* __restrict__ A, const float* __restrict__ B,
    const float* __restrict__ bias, float* __restrict__ C,
    int M, int N, int K)
{
    const int BM = 128, BN = 128, BK = 8;
    __shared__ float As[BK][BM];       // transposed A tile
    __shared__ float Bs[BK][BN];

    const int tid  = threadIdx.x;
    const int cRow = blockIdx.y;
    const int cCol = blockIdx.x;

    // A tile load mapping: one float4 per thread. row 0..127, col group 0/1
    const int aRow = tid >> 1;
    const int aCol = (tid & 1) << 2;
    // B tile load mapping: row 0..7, 4 consecutive floats
    const int bRow = tid >> 5;
    const int bCol = (tid & 31) << 2;

    const float* Aptr = A + (size_t)cRow * BM * K;
    const float* Bptr = B + (size_t)cCol * BN;

    const int tr = (tid >> 4) << 3;   // 0..120 step 8
    const int tc = (tid & 15) << 3;   // 0..120 step 8

    float acc[8][8];
    #pragma unroll
    for (int i = 0; i < 8; i++)
        #pragma unroll
        for (int j = 0; j < 8; j++) acc[i][j] = 0.f;

    for (int k0 = 0; k0 < K; k0 += BK) {
        float4 av = *reinterpret_cast<const float4*>(Aptr + (size_t)aRow * K + k0 + aCol);
        As[aCol + 0][aRow] = av.x;
        As[aCol + 1][aRow] = av.y;
        As[aCol + 2][aRow] = av.z;
        As[aCol + 3][aRow] = av.w;
        float4 bv = *reinterpret_cast<const float4*>(Bptr + (size_t)(k0 + bRow) * N + bCol);
        *reinterpret_cast<float4*>(&Bs[bRow][bCol]) = bv;
        __syncthreads();

        #pragma unroll
        for (int k = 0; k < BK; k++) {
            float ra[8], rb[8];
            #pragma unroll
            for (int i = 0; i < 8; i++) ra[i] = As[k][tr + i];
            #pragma unroll
            for (int j = 0; j < 8; j++) rb[j] = Bs[k][tc + j];
            #pragma unroll
            for (int i = 0; i < 8; i++)
                #pragma unroll
                for (int j = 0; j < 8; j++)
                    acc[i][j] = fmaf(ra[i], rb[j], acc[i][j]);
        }
        __syncthreads();
    }

    // epilogue: add bias, write
    float bvals[8];
    #pragma unroll
    for (int j = 0; j < 8; j++) bvals[j] = bias[cCol * BN + tc + j];

    float* Cptr = C + (size_t)(cRow * BM) * N + cCol * BN;
    #pragma unroll
    for (int i = 0; i < 8; i++) {
        float4 v0, v1;
        v0.x = acc[i][0] + bvals[0];
        v0.y = acc[i][1] + bvals[1];
        v0.z = acc[i][2] + bvals[2];
        v0.w = acc[i][3] + bvals[3];
        v1.x = acc[i][4] + bvals[4];
        v1.y = acc[i][5] + bvals[5];
        v1.z = acc[i][6] + bvals[6];
        v1.w = acc[i][7] + bvals[7];
        float* row = Cptr + (size_t)(tr + i) * N + tc;
        *reinterpret_cast<float4*>(row)     = v0;
        *reinterpret_cast<float4*>(row + 4) = v1;
    }
}

// ---------------------------------------------------------------------------
// Causal flash attention, fp32.
// Grid: (qblocks=32, NH=16, B=2). Block: 256 threads.
// Tile: BQ=64 query rows, BKV=32 kv rows, HD=64.
// Thread (r = tid/4, g = tid&3): owns score cols {c = cc*4+g, cc=0..7}
// and output dims d in [g*16, g*16+16).
// ---------------------------------------------------------------------------
#define BQ  64
#define BKV 32
#define NEG_BIG (-1e30f)

__global__ __launch_bounds__(256) void flash_causal_kernel(
    const float* __restrict__ qkv, float* __restrict__ attn_out)
{
    __shared__ float Qs[BQ][HDIM + 4];   // stride 68 words: conflict-free row reads
    __shared__ float Ks[BKV][HDIM + 4];
    __shared__ float Vs[BKV][HDIM + 4];
    __shared__ float Ps[BQ][BKV + 1];    // stride 33: conflict-free

    const int qb  = blockIdx.x;
    const int h   = blockIdx.y;
    const int b   = blockIdx.z;
    const int tid = threadIdx.x;
    const int q0  = qb * BQ;

    // --- load Q tile (64 rows x 64 floats) ---
    for (int i = tid; i < BQ * (HDIM / 4); i += 256) {
        int rr = i >> 4, c4 = (i & 15);
        const float4 qv = *reinterpret_cast<const float4*>(
            qkv + (size_t)(b * SEQ + q0 + rr) * 3072 + h * HDIM + c4 * 4);
        *reinterpret_cast<float4*>(&Qs[rr][c4 * 4]) = qv;
    }

    const int r = tid >> 2;     // query row within tile, 0..63
    const int g = tid & 3;      // quad lane, 0..3
    const int rg = q0 + r;      // global query row

    float m = NEG_BIG, l = 0.f;
    float acc[16];
    #pragma unroll
    for (int j = 0; j < 16; j++) acc[j] = 0.f;

    const int nkv = 2 * qb + 2;           // tiles covering [0, q0+63]
    for (int t = 0; t < nkv; t++) {
        const int kv0 = t * BKV;
        __syncthreads();                  // Ks/Vs reuse safety (covers Q load at t=0)

        // --- load K,V tiles (32 x 64 each) ---
        for (int i = tid; i < BKV * (HDIM / 4); i += 256) {
            int rr = i >> 4, c4 = (i & 15);
            size_t base = (size_t)(b * SEQ + kv0 + rr) * 3072 + h * HDIM + c4 * 4;
            *reinterpret_cast<float4*>(&Ks[rr][c4 * 4]) =
                *reinterpret_cast<const float4*>(qkv + base + 1024);
            *reinterpret_cast<float4*>(&Vs[rr][c4 * 4]) =
                *reinterpret_cast<const float4*>(qkv + base + 2048);
        }
        __syncthreads();

        // --- scores: this thread's 8 columns c = cc*4+g ---
        float s[8];
        #pragma unroll
        for (int cc = 0; cc < 8; cc++) s[cc] = 0.f;
        #pragma unroll
        for (int d4 = 0; d4 < 16; d4++) {
            float4 q4 = *reinterpret_cast<const float4*>(&Qs[r][d4 * 4]);
            #pragma unroll
            for (int cc = 0; cc < 8; cc++) {
                float4 k4 = *reinterpret_cast<const float4*>(&Ks[cc * 4 + g][d4 * 4]);
                s[cc] = fmaf(q4.x, k4.x, s[cc]);
                s[cc] = fmaf(q4.y, k4.y, s[cc]);
                s[cc] = fmaf(q4.z, k4.z, s[cc]);
                s[cc] = fmaf(q4.w, k4.w, s[cc]);
            }
        }

        const float scale = 0.125f;   // 1/sqrt(64)
        const bool need_mask = (kv0 + BKV - 1 > q0);
        float tmax = NEG_BIG;
        #pragma unroll
        for (int cc = 0; cc < 8; cc++) {
            s[cc] *= scale;
            if (need_mask && (kv0 + cc * 4 + g > rg)) s[cc] = NEG_BIG;
            tmax = fmaxf(tmax, s[cc]);
        }
        // quad reduce (4 lanes share a row; lanes differ in 2 LSBs)
        tmax = fmaxf(tmax, __shfl_xor_sync(0xffffffffu, tmax, 1));
        tmax = fmaxf(tmax, __shfl_xor_sync(0xffffffffu, tmax, 2));
        const float m_new = fmaxf(m, tmax);
        const float alpha = __expf(m - m_new);

        float psum = 0.f;
        #pragma unroll
        for (int cc = 0; cc < 8; cc++) {
            float p = __expf(s[cc] - m_new);
            Ps[r][cc * 4 + g] = p;
            psum += p;
        }
        psum += __shfl_xor_sync(0xffffffffu, psum, 1);
        psum += __shfl_xor_sync(0xffffffffu, psum, 2);
        l = l * alpha + psum;
        m = m_new;

        #pragma unroll
        for (int j = 0; j < 16; j++) acc[j] *= alpha;

        __syncwarp();   // Ps row written by this thread's own quad (same warp)

        // --- O += P @ V on this thread's 16 dims [g*16, g*16+16) ---
        #pragma unroll
        for (int c = 0; c < BKV; c++) {
            float p = Ps[r][c];
            const float* vrow = &Vs[c][g * 16];
            float4 v0 = *reinterpret_cast<const float4*>(vrow);
            float4 v1 = *reinterpret_cast<const float4*>(vrow + 4);
            float4 v2 = *reinterpret_cast<const float4*>(vrow + 8);
            float4 v3 = *reinterpret_cast<const float4*>(vrow + 12);
            acc[0]  = fmaf(p, v0.x, acc[0]);
            acc[1]  = fmaf(p, v0.y, acc[1]);
            acc[2]  = fmaf(p, v0.z, acc[2]);
            acc[3]  = fmaf(p, v0.w, acc[3]);
            acc[4]  = fmaf(p, v1.x, acc[4]);
            acc[5]  = fmaf(p, v1.y, acc[5]);
            acc[6]  = fmaf(p, v1.z, acc[6]);
            acc[7]  = fmaf(p, v1.w, acc[7]);
            acc[8]  = fmaf(p, v2.x, acc[8]);
            acc[9]  = fmaf(p, v2.y, acc[9]);
            acc[10] = fmaf(p, v2.z, acc[10]);
            acc[11] = fmaf(p, v2.w, acc[11]);
            acc[12] = fmaf(p, v3.x, acc[12]);
            acc[13] = fmaf(p, v3.y, acc[13]);
            acc[14] = fmaf(p, v3.z, acc[14]);
            acc[15] = fmaf(p, v3.w, acc[15]);
        }
    }

    // --- finalize: divide by l, write (B,S,NH,HD) ---
    const float inv = 1.f / l;
    float* op = attn_out + (size_t)(b * SEQ + rg) * HID + h * HDIM + g * 16;
    #pragma unroll
    for (int j4 = 0; j4 < 4; j4++) {
        float4 v;
        v.x = acc[j4 * 4 + 0] * inv;
        v.y = acc[j4 * 4 + 1] * inv;
        v.z = acc[j4 * 4 + 2] * inv;
        v.w = acc[j4 * 4 + 3] * inv;
        *reinterpret_cast<float4*>(op + j4 * 4) = v;
    }
}

// ---------------------------------------------------------------------------
extern "C" void kernel_launch(void* const* d_in, const int* in_sizes, int n_in,
                              void* d_out, int out_size)
{
    const float* x     = (const float*)d_in[0];
    const float* w_qkv = (const float*)d_in[1];
    const float* b_qkv = (const float*)d_in[2];
    const float* w_out = (const float*)d_in[3];
    const float* b_out = (const float*)d_in[4];
    float* out = (float*)d_out;

    float *qkv = nullptr, *attn = nullptr;
    cudaGetSymbolAddress((void**)&qkv,  g_qkv);
    cudaGetSymbolAddress((void**)&attn, g_attn);

    // 1) qkv = x @ w_qkv + b_qkv   (4096 x 3072 x 1024)
    dim3 g1(3 * HID / 128, NTOK / 128);
    sgemm_bias_kernel<<<g1, 256>>>(x, w_qkv, b_qkv, qkv, NTOK, 3 * HID, HID);

    // 2) causal flash attention
    dim3 g2(SEQ / BQ, NHEAD, BATCH);
    flash_causal_kernel<<<g2, 256>>>(qkv, attn);

    // 3) out = attn @ w_out + b_out  (4096 x 1024 x 1024)
    dim3 g3(HID / 128, NTOK / 128);
    sgemm_bias_kernel<<<g3, 256>>>(attn, w_out, b_out, out, NTOK, HID, HID);
}

// round 2
// speedup vs baseline: 5.0584x; 5.0584x over previous
#include <cuda_runtime.h>
#include <cstdint>

#define BATCH 2
#define SEQ   2048
#define HID   1024
#define NHEAD 16
#define HDIM  64
#define NTOK  (BATCH*SEQ)

// Scratch (device globals: allocation-free rule)
__device__ float g_qkv[NTOK * 3 * HID];   // (B,S,3,NH,HD)
__device__ float g_attn[NTOK * HID];      // (B,S,NH,HD)

// ---------------------------------------------------------------------------
// helpers
// ---------------------------------------------------------------------------
__device__ __forceinline__ float tf32f(float x) {
    uint32_t u;
    asm("cvt.rna.tf32.f32 %0, %1;" : "=r"(u) : "f"(x));
    return __uint_as_float(u);
}

__device__ __forceinline__ void mma8(float* c,
                                     uint32_t a0, uint32_t a1, uint32_t a2, uint32_t a3,
                                     uint32_t b0, uint32_t b1) {
    asm volatile(
        "mma.sync.aligned.m16n8k8.row.col.f32.tf32.tf32.f32 "
        "{%0,%1,%2,%3}, {%4,%5,%6,%7}, {%8,%9}, {%0,%1,%2,%3};"
        : "+f"(c[0]), "+f"(c[1]), "+f"(c[2]), "+f"(c[3])
        : "r"(a0), "r"(a1), "r"(a2), "r"(a3), "r"(b0), "r"(b1));
}

__device__ __forceinline__ uint32_t fbits(float x) { return __float_as_uint(x); }

// ---------------------------------------------------------------------------
// TF32 GEMM: C = A(M,K) * B(K,N) + bias, row-major. 128x128x32 block tile,
// 8 warps (2x4), warp tile 64x32 via m16n8k8. Dims are tile multiples.
// ---------------------------------------------------------------------------
__global__ __launch_bounds__(256) void gemm_tf32(
    const float* __restrict__ A, const float* __restrict__ B,
    const float* __restrict__ bias, float* __restrict__ C,
    int M, int N, int K)
{
    __shared__ float As[128][36];   // [m][k] pad->conflict-free frag loads
    __shared__ float Bs[32][132];   // [k][n]

    const int tid  = threadIdx.x;
    const int warp = tid >> 5, lane = tid & 31;
    const int wm = warp >> 2, wn = warp & 3;   // 2 x 4 warp grid
    const int g2 = lane >> 2, t4 = lane & 3;
    const int cRow = blockIdx.y, cCol = blockIdx.x;

    const float* Ab = A + (size_t)cRow * 128 * K;
    const float* Bb = B + cCol * 128;

    float c[4][4][4];
    #pragma unroll
    for (int mf = 0; mf < 4; mf++)
        #pragma unroll
        for (int nf = 0; nf < 4; nf++)
            #pragma unroll
            for (int i = 0; i < 4; i++) c[mf][nf][i] = 0.f;

    for (int k0 = 0; k0 < K; k0 += 32) {
        // A tile: 128x32 = 1024 float4, 4 per thread
        #pragma unroll
        for (int i = 0; i < 4; i++) {
            int idx = tid + i * 256;
            int r = idx >> 3, c4 = (idx & 7) << 2;
            float4 v = *reinterpret_cast<const float4*>(Ab + (size_t)r * K + k0 + c4);
            float4 w = make_float4(tf32f(v.x), tf32f(v.y), tf32f(v.z), tf32f(v.w));
            *reinterpret_cast<float4*>(&As[r][c4]) = w;
        }
        // B tile: 32x128 = 1024 float4
        #pragma unroll
        for (int i = 0; i < 4; i++) {
            int idx = tid + i * 256;
            int r = idx >> 5, c4 = (idx & 31) << 2;
            float4 v = *reinterpret_cast<const float4*>(Bb + (size_t)(k0 + r) * N + c4);
            float4 w = make_float4(tf32f(v.x), tf32f(v.y), tf32f(v.z), tf32f(v.w));
            *reinterpret_cast<float4*>(&Bs[r][c4]) = w;
        }
        __syncthreads();

        #pragma unroll
        for (int ks = 0; ks < 4; ks++) {
            const int k = ks * 8;
            uint32_t a[4][4], b[4][2];
            #pragma unroll
            for (int mf = 0; mf < 4; mf++) {
                int r0 = wm * 64 + mf * 16 + g2;
                a[mf][0] = fbits(As[r0][k + t4]);
                a[mf][1] = fbits(As[r0 + 8][k + t4]);
                a[mf][2] = fbits(As[r0][k + 4 + t4]);
                a[mf][3] = fbits(As[r0 + 8][k + 4 + t4]);
            }
            #pragma unroll
            for (int nf = 0; nf < 4; nf++) {
                int cc = wn * 32 + nf * 8 + g2;
                b[nf][0] = fbits(Bs[k + t4][cc]);
                b[nf][1] = fbits(Bs[k + 4 + t4][cc]);
            }
            #pragma unroll
            for (int mf = 0; mf < 4; mf++)
                #pragma unroll
                for (int nf = 0; nf < 4; nf++)
                    mma8(c[mf][nf], a[mf][0], a[mf][1], a[mf][2], a[mf][3],
                         b[nf][0], b[nf][1]);
        }
        __syncthreads();
    }

    // epilogue: bias + store (float2 per fragment row)
    #pragma unroll
    for (int nf = 0; nf < 4; nf++) {
        int cc = cCol * 128 + wn * 32 + nf * 8 + t4 * 2;
        float b0 = bias[cc], b1 = bias[cc + 1];
        #pragma unroll
        for (int mf = 0; mf < 4; mf++) {
            int r0 = cRow * 128 + wm * 64 + mf * 16 + g2;
            float2 v0 = make_float2(c[mf][nf][0] + b0, c[mf][nf][1] + b1);
            float2 v1 = make_float2(c[mf][nf][2] + b0, c[mf][nf][3] + b1);
            *reinterpret_cast<float2*>(C + (size_t)r0 * N + cc)       = v0;
            *reinterpret_cast<float2*>(C + (size_t)(r0 + 8) * N + cc) = v1;
        }
    }
}

// ---------------------------------------------------------------------------
// TF32 causal flash attention. BQ=64, BKV=32, 256 threads (8 warps).
// S phase:  warp (wq = w>>1, wh = w&1): rows wq*16..+16, kv cols wh*16..+16
// PV phase: warp (wq, wd = w&1):        rows wq*16..+16, dims wd*32..+32
// Softmax:  thread (r=tid>>2, g=tid&3): row r, cols j = g + 4*jj
// ---------------------------------------------------------------------------
#define BQ  64
#define BKV 32

__global__ __launch_bounds__(256) void flash_tf32(
    const float* __restrict__ qkv, float* __restrict__ attn_out)
{
    __shared__ float Qs[BQ][68];
    __shared__ float Ks[BKV][68];
    __shared__ float Vs[BKV][72];
    __shared__ float Ss[BQ][36];
    __shared__ float alphas[BQ];
    __shared__ float linv[BQ];

    const int qb = blockIdx.x, h = blockIdx.y, b = blockIdx.z;
    const int tid = threadIdx.x, warp = tid >> 5, lane = tid & 31;
    const int g2 = lane >> 2, t4 = lane & 3;
    const int q0 = qb * BQ;
    const int wq = warp >> 1, wh = warp & 1;

    // Q tile, pre-scaled by 1/sqrt(64)=0.125, converted to tf32
    #pragma unroll
    for (int i = 0; i < 4; i++) {
        int idx = tid + i * 256;
        int r = idx >> 4, c4 = (idx & 15) << 2;
        float4 v = *reinterpret_cast<const float4*>(
            qkv + (size_t)(b * SEQ + q0 + r) * 3072 + h * 64 + c4);
        float4 w = make_float4(tf32f(v.x * 0.125f), tf32f(v.y * 0.125f),
                               tf32f(v.z * 0.125f), tf32f(v.w * 0.125f));
        *reinterpret_cast<float4*>(&Qs[r][c4]) = w;
    }

    const int sr = tid >> 2, sg = tid & 3;
    const int rg = q0 + sr;
    float m = -1e30f, l = 0.f;
    float o[4][4];
    #pragma unroll
    for (int nf = 0; nf < 4; nf++)
        #pragma unroll
        for (int i = 0; i < 4; i++) o[nf][i] = 0.f;

    const int nkv = 2 * qb + 2;
    for (int t = 0; t < nkv; t++) {
        const int kv0 = t * BKV;
        __syncthreads();   // protect Ks/Vs/Ss reuse (covers Q load at t=0)

        // K,V tiles: 32x64 each, tf32
        #pragma unroll
        for (int i = 0; i < 2; i++) {
            int idx = tid + i * 256;
            int r = idx >> 4, c4 = (idx & 15) << 2;
            size_t base = (size_t)(b * SEQ + kv0 + r) * 3072 + h * 64 + c4;
            float4 kv = *reinterpret_cast<const float4*>(qkv + base + 1024);
            float4 vv = *reinterpret_cast<const float4*>(qkv + base + 2048);
            *reinterpret_cast<float4*>(&Ks[r][c4]) =
                make_float4(tf32f(kv.x), tf32f(kv.y), tf32f(kv.z), tf32f(kv.w));
            *reinterpret_cast<float4*>(&Vs[r][c4]) =
                make_float4(tf32f(vv.x), tf32f(vv.y), tf32f(vv.z), tf32f(vv.w));
        }
        __syncthreads();

        // ---- S = Q @ K^T (scaled) ----
        float s[2][4];
        #pragma unroll
        for (int nf = 0; nf < 2; nf++)
            #pragma unroll
            for (int i = 0; i < 4; i++) s[nf][i] = 0.f;

        #pragma unroll
        for (int ks = 0; ks < 8; ks++) {
            const int k = ks * 8;
            const int r0 = wq * 16 + g2;
            uint32_t a0 = fbits(Qs[r0][k + t4]);
            uint32_t a1 = fbits(Qs[r0 + 8][k + t4]);
            uint32_t a2 = fbits(Qs[r0][k + 4 + t4]);
            uint32_t a3 = fbits(Qs[r0 + 8][k + 4 + t4]);
            #pragma unroll
            for (int nf = 0; nf < 2; nf++) {
                int cc = wh * 16 + nf * 8 + g2;
                uint32_t b0 = fbits(Ks[cc][k + t4]);
                uint32_t b1 = fbits(Ks[cc][k + 4 + t4]);
                mma8(s[nf], a0, a1, a2, a3, b0, b1);
            }
        }
        // store scores
        #pragma unroll
        for (int nf = 0; nf < 2; nf++) {
            int cc = wh * 16 + nf * 8 + t4 * 2;
            int r0 = wq * 16 + g2;
            *reinterpret_cast<float2*>(&Ss[r0][cc])     = make_float2(s[nf][0], s[nf][1]);
            *reinterpret_cast<float2*>(&Ss[r0 + 8][cc]) = make_float2(s[nf][2], s[nf][3]);
        }
        __syncthreads();

        // ---- online softmax (scalar, conflict-free col mapping) ----
        const bool need_mask = (kv0 + BKV - 1 > q0);
        float sv[8];
        float tmax = -1e30f;
        #pragma unroll
        for (int jj = 0; jj < 8; jj++) {
            int j = sg + jj * 4;
            float x = Ss[sr][j];
            if (need_mask && (kv0 + j > rg)) x = -1e30f;
            sv[jj] = x;
            tmax = fmaxf(tmax, x);
        }
        tmax = fmaxf(tmax, __shfl_xor_sync(0xffffffffu, tmax, 1));
        tmax = fmaxf(tmax, __shfl_xor_sync(0xffffffffu, tmax, 2));
        const float m_new = fmaxf(m, tmax);
        const float alpha = __expf(m - m_new);
        float psum = 0.f;
        #pragma unroll
        for (int jj = 0; jj < 8; jj++) {
            float p = __expf(sv[jj] - m_new);
            Ss[sr][sg + jj * 4] = tf32f(p);
            psum += p;
        }
        psum += __shfl_xor_sync(0xffffffffu, psum, 1);
        psum += __shfl_xor_sync(0xffffffffu, psum, 2);
        l = l * alpha + psum;
        m = m_new;
        if (sg == 0) alphas[sr] = alpha;
        __syncthreads();

        // ---- O = alpha*O + P @ V ----
        const float av0 = alphas[wq * 16 + g2];
        const float av1 = alphas[wq * 16 + 8 + g2];
        #pragma unroll
        for (int nf = 0; nf < 4; nf++) {
            o[nf][0] *= av0; o[nf][1] *= av0;
            o[nf][2] *= av1; o[nf][3] *= av1;
        }
        #pragma unroll
        for (int ks = 0; ks < 4; ks++) {
            const int k = ks * 8;
            const int r0 = wq * 16 + g2;
            uint32_t a0 = fbits(Ss[r0][k + t4]);
            uint32_t a1 = fbits(Ss[r0 + 8][k + t4]);
            uint32_t a2 = fbits(Ss[r0][k + 4 + t4]);
            uint32_t a3 = fbits(Ss[r0 + 8][k + 4 + t4]);
            #pragma unroll
            for (int nf = 0; nf < 4; nf++) {
                int cc = wh * 32 + nf * 8 + g2;
                uint32_t b0 = fbits(Vs[k + t4][cc]);
                uint32_t b1 = fbits(Vs[k + 4 + t4][cc]);
                mma8(o[nf], a0, a1, a2, a3, b0, b1);
            }
        }
    }

    __syncthreads();
    if (sg == 0) linv[sr] = 1.0f / l;
    __syncthreads();

    const float li0 = linv[wq * 16 + g2];
    const float li1 = linv[wq * 16 + 8 + g2];
    #pragma unroll
    for (int nf = 0; nf < 4; nf++) {
        int cc = wh * 32 + nf * 8 + t4 * 2;
        int r0 = wq * 16 + g2;
        float* p0 = attn_out + (size_t)(b * SEQ + q0 + r0) * HID + h * 64 + cc;
        float* p1 = attn_out + (size_t)(b * SEQ + q0 + r0 + 8) * HID + h * 64 + cc;
        *reinterpret_cast<float2*>(p0) = make_float2(o[nf][0] * li0, o[nf][1] * li0);
        *reinterpret_cast<float2*>(p1) = make_float2(o[nf][2] * li1, o[nf][3] * li1);
    }
}

// ---------------------------------------------------------------------------
extern "C" void kernel_launch(void* const* d_in, const int* in_sizes, int n_in,
                              void* d_out, int out_size)
{
    const float* x     = (const float*)d_in[0];
    const float* w_qkv = (const float*)d_in[1];
    const float* b_qkv = (const float*)d_in[2];
    const float* w_out = (const float*)d_in[3];
    const float* b_out = (const float*)d_in[4];
    float* out = (float*)d_out;

    float *qkv = nullptr, *attn = nullptr;
    cudaGetSymbolAddress((void**)&qkv,  g_qkv);
    cudaGetSymbolAddress((void**)&attn, g_attn);

    // 1) qkv = x @ w_qkv + b_qkv   (4096 x 3072 x 1024)
    dim3 g1(3 * HID / 128, NTOK / 128);
    gemm_tf32<<<g1, 256>>>(x, w_qkv, b_qkv, qkv, NTOK, 3 * HID, HID);

    // 2) causal flash attention (tf32 tensor cores)
    dim3 g2(SEQ / BQ, NHEAD, BATCH);
    flash_tf32<<<g2, 256>>>(qkv, attn);

    // 3) out = attn @ w_out + b_out  (4096 x 1024 x 1024)
    dim3 g3(HID / 128, NTOK / 128);
    gemm_tf32<<<g3, 256>>>(attn, w_out, b_out, out, NTOK, HID, HID);
}

// round 3
// speedup vs baseline: 5.6526x; 1.1175x over previous
#include <cuda_runtime.h>
#include <cstdint>

#define BATCH 2
#define SEQ   2048
#define HID   1024
#define NHEAD 16
#define HDIM  64
#define NTOK  (BATCH*SEQ)

// Scratch (device globals: allocation-free rule)
__device__ float g_qkv[NTOK * 3 * HID];   // (B,S,3,NH,HD) pre-rounded tf32
__device__ float g_attn[NTOK * HID];      // pre-rounded tf32
__device__ float g_xc[NTOK * HID];        // x rounded to tf32
__device__ float g_w1[HID * 3 * HID];     // w_qkv rounded
__device__ float g_w2[HID * HID];         // w_out rounded

// ---------------------------------------------------------------------------
// helpers
// ---------------------------------------------------------------------------
__device__ __forceinline__ float tf32f(float x) {
    uint32_t u;
    asm("cvt.rna.tf32.f32 %0, %1;" : "=r"(u) : "f"(x));
    return __uint_as_float(u);
}
__device__ __forceinline__ uint32_t fbits(float x) { return __float_as_uint(x); }
__device__ __forceinline__ uint32_t smem_u32(const void* p) {
    return (uint32_t)__cvta_generic_to_shared(p);
}
#define CP16(dst_u32, src_ptr) \
    asm volatile("cp.async.ca.shared.global [%0], [%1], 16;" :: "r"(dst_u32), "l"(src_ptr))
#define CP_COMMIT() asm volatile("cp.async.commit_group;")
#define CP_WAIT1()  asm volatile("cp.async.wait_group 1;")

__device__ __forceinline__ void mma8(float* c,
                                     uint32_t a0, uint32_t a1, uint32_t a2, uint32_t a3,
                                     uint32_t b0, uint32_t b1) {
    asm volatile(
        "mma.sync.aligned.m16n8k8.row.col.f32.tf32.tf32.f32 "
        "{%0,%1,%2,%3}, {%4,%5,%6,%7}, {%8,%9}, {%0,%1,%2,%3};"
        : "+f"(c[0]), "+f"(c[1]), "+f"(c[2]), "+f"(c[3])
        : "r"(a0), "r"(a1), "r"(a2), "r"(a3), "r"(b0), "r"(b1));
}

// ---------------------------------------------------------------------------
// tf32 rounding prepass (float4 grid-stride)
// ---------------------------------------------------------------------------
__global__ void round_tf32_kernel(const float* __restrict__ in,
                                  float* __restrict__ out, int n4)
{
    int i = blockIdx.x * blockDim.x + threadIdx.x;
    if (i < n4) {
        float4 v = reinterpret_cast<const float4*>(in)[i];
        reinterpret_cast<float4*>(out)[i] =
            make_float4(tf32f(v.x), tf32f(v.y), tf32f(v.z), tf32f(v.w));
    }
}

// ---------------------------------------------------------------------------
// TF32 GEMM, cp.async 2-stage pipeline. 128x128x32 tile, 8 warps (2x4),
// inputs pre-rounded to tf32. round_out: round stored C to tf32.
// ---------------------------------------------------------------------------
#define GA_STRIDE 36
#define GB_STRIDE 132
#define GEMM_SMEM ((2*128*GA_STRIDE + 2*32*GB_STRIDE) * 4)   // 70656 B

__global__ __launch_bounds__(256, 2) void gemm_tf32(
    const float* __restrict__ A, const float* __restrict__ B,
    const float* __restrict__ bias, float* __restrict__ C,
    int M, int N, int K, int round_out)
{
    extern __shared__ float sm[];
    float* As = sm;                        // [2][128][36]
    float* Bs = sm + 2 * 128 * GA_STRIDE;  // [2][32][132]

    const int tid  = threadIdx.x;
    const int warp = tid >> 5, lane = tid & 31;
    const int wm = warp >> 2, wn = warp & 3;
    const int g2 = lane >> 2, t4 = lane & 3;
    const int cRow = blockIdx.y, cCol = blockIdx.x;

    const float* Ab = A + (size_t)cRow * 128 * K;
    const float* Bb = B + cCol * 128;

    // per-thread load coords
    const int ar = tid >> 3, ac = (tid & 7) << 2;     // +i*32 rows
    const int br = tid >> 5, bc = (tid & 31) << 2;    // +i*8 rows

    float c[4][4][4];
    #pragma unroll
    for (int mf = 0; mf < 4; mf++)
        #pragma unroll
        for (int nf = 0; nf < 4; nf++)
            #pragma unroll
            for (int i = 0; i < 4; i++) c[mf][nf][i] = 0.f;

    const int nk = K >> 5;

    // prefetch stage 0
    {
        float* Ad = As; float* Bd = Bs;
        #pragma unroll
        for (int i = 0; i < 4; i++) {
            int r = ar + i * 32;
            CP16(smem_u32(Ad + r * GA_STRIDE + ac), Ab + (size_t)r * K + ac);
        }
        #pragma unroll
        for (int i = 0; i < 4; i++) {
            int r = br + i * 8;
            CP16(smem_u32(Bd + r * GB_STRIDE + bc), Bb + (size_t)r * N + bc);
        }
        CP_COMMIT();
    }

    for (int it = 0; it < nk; it++) {
        // prefetch next stage (or empty group)
        if (it + 1 < nk) {
            const int k0 = (it + 1) << 5;
            float* Ad = As + ((it + 1) & 1) * 128 * GA_STRIDE;
            float* Bd = Bs + ((it + 1) & 1) * 32 * GB_STRIDE;
            #pragma unroll
            for (int i = 0; i < 4; i++) {
                int r = ar + i * 32;
                CP16(smem_u32(Ad + r * GA_STRIDE + ac), Ab + (size_t)r * K + k0 + ac);
            }
            #pragma unroll
            for (int i = 0; i < 4; i++) {
                int r = br + i * 8;
                CP16(smem_u32(Bd + r * GB_STRIDE + bc), Bb + (size_t)(k0 + r) * N + bc);
            }
        }
        CP_COMMIT();
        CP_WAIT1();
        __syncthreads();

        const float* Ac = As + (it & 1) * 128 * GA_STRIDE;
        const float* Bc = Bs + (it & 1) * 32 * GB_STRIDE;

        #pragma unroll
        for (int ks = 0; ks < 4; ks++) {
            const int k = ks * 8;
            uint32_t a[4][4], b[4][2];
            #pragma unroll
            for (int mf = 0; mf < 4; mf++) {
                int r0 = wm * 64 + mf * 16 + g2;
                a[mf][0] = fbits(Ac[r0 * GA_STRIDE + k + t4]);
                a[mf][1] = fbits(Ac[(r0 + 8) * GA_STRIDE + k + t4]);
                a[mf][2] = fbits(Ac[r0 * GA_STRIDE + k + 4 + t4]);
                a[mf][3] = fbits(Ac[(r0 + 8) * GA_STRIDE + k + 4 + t4]);
            }
            #pragma unroll
            for (int nf = 0; nf < 4; nf++) {
                int cc = wn * 32 + nf * 8 + g2;
                b[nf][0] = fbits(Bc[(k + t4) * GB_STRIDE + cc]);
                b[nf][1] = fbits(Bc[(k + 4 + t4) * GB_STRIDE + cc]);
            }
            #pragma unroll
            for (int mf = 0; mf < 4; mf++)
                #pragma unroll
                for (int nf = 0; nf < 4; nf++)
                    mma8(c[mf][nf], a[mf][0], a[mf][1], a[mf][2], a[mf][3],
                         b[nf][0], b[nf][1]);
        }
        __syncthreads();
    }

    #pragma unroll
    for (int nf = 0; nf < 4; nf++) {
        int cc = cCol * 128 + wn * 32 + nf * 8 + t4 * 2;
        float b0 = bias[cc], b1 = bias[cc + 1];
        #pragma unroll
        for (int mf = 0; mf < 4; mf++) {
            int r0 = cRow * 128 + wm * 64 + mf * 16 + g2;
            float v00 = c[mf][nf][0] + b0, v01 = c[mf][nf][1] + b1;
            float v10 = c[mf][nf][2] + b0, v11 = c[mf][nf][3] + b1;
            if (round_out) {
                v00 = tf32f(v00); v01 = tf32f(v01);
                v10 = tf32f(v10); v11 = tf32f(v11);
            }
            *reinterpret_cast<float2*>(C + (size_t)r0 * N + cc)       = make_float2(v00, v01);
            *reinterpret_cast<float2*>(C + (size_t)(r0 + 8) * N + cc) = make_float2(v10, v11);
        }
    }
}

// ---------------------------------------------------------------------------
// TF32 causal flash attention. BQ=64, BKV=64, 256 threads, cp.async 2-stage KV.
// S phase:  warp (wq=w>>1, wh=w&1): rows wq*16..+16, cols wh*32..+32
// Softmax:  thread (sr=tid>>2, sg=tid&3): row sr, cols j = sg + 4*jj (16 cols)
// PV phase: same warp tiling, dims wh*32..+32, K-dim 64
// ---------------------------------------------------------------------------
#define BQ  64
#define BKV 64
#define QS_S 68
#define KS_S 68
#define VS_S 72
#define SS_S 68
#define FLASH_SMEM ((64*QS_S + 2*64*KS_S + 2*64*VS_S + 64*SS_S + 128) * 4) // 107008 B

__global__ __launch_bounds__(256, 2) void flash_tf32(
    const float* __restrict__ qkv, float* __restrict__ attn_out)
{
    extern __shared__ float sm[];
    float* Qs = sm;                                  // [64][68]
    float* Ks = sm + 64 * QS_S;                      // [2][64][68]
    float* Vs = Ks + 2 * 64 * KS_S;                  // [2][64][72]
    float* Ss = Vs + 2 * 64 * VS_S;                  // [64][68]
    float* alphas = Ss + 64 * SS_S;                  // [64]
    float* linv   = alphas + 64;                     // [64]

    const int qb = gridDim.x - 1 - blockIdx.x;       // heavy blocks first
    const int h = blockIdx.y, b = blockIdx.z;
    const int tid = threadIdx.x, warp = tid >> 5, lane = tid & 31;
    const int g2 = lane >> 2, t4 = lane & 3;
    const int q0 = qb * BQ;
    const int wq = warp >> 1, wh = warp & 1;

    // KV tile copy coords: 1024 float4 per matrix, 4+4 per thread
    const int kr = tid >> 4, kc = (tid & 15) << 2;

    // Q tile: scale by 0.125 (exact on tf32-rounded input)
    #pragma unroll
    for (int i = 0; i < 4; i++) {
        int idx = tid + i * 256;
        int r = idx >> 4, c4 = (idx & 15) << 2;
        float4 v = *reinterpret_cast<const float4*>(
            qkv + (size_t)(b * SEQ + q0 + r) * 3072 + h * 64 + c4);
        Qs[r * QS_S + c4 + 0] = v.x * 0.125f;
        Qs[r * QS_S + c4 + 1] = v.y * 0.125f;
        Qs[r * QS_S + c4 + 2] = v.z * 0.125f;
        Qs[r * QS_S + c4 + 3] = v.w * 0.125f;
    }

    const int sr = tid >> 2, sg = tid & 3;
    const int rg = q0 + sr;
    float m = -1e30f, l = 0.f;
    float o[4][4];
    #pragma unroll
    for (int nf = 0; nf < 4; nf++)
        #pragma unroll
        for (int i = 0; i < 4; i++) o[nf][i] = 0.f;

    const int nkv = qb + 1;

    // prefetch KV tile 0
    {
        float* Kd = Ks; float* Vd = Vs;
        #pragma unroll
        for (int i = 0; i < 4; i++) {
            int r = kr + i * 16;
            size_t base = (size_t)(b * SEQ + r) * 3072 + h * 64 + kc;
            CP16(smem_u32(Kd + r * KS_S + kc), qkv + base + 1024);
            CP16(smem_u32(Vd + r * VS_S + kc), qkv + base + 2048);
        }
        CP_COMMIT();
    }

    for (int t = 0; t < nkv; t++) {
        if (t + 1 < nkv) {
            const int kv1 = (t + 1) * BKV;
            float* Kd = Ks + ((t + 1) & 1) * 64 * KS_S;
            float* Vd = Vs + ((t + 1) & 1) * 64 * VS_S;
            #pragma unroll
            for (int i = 0; i < 4; i++) {
                int r = kr + i * 16;
                size_t base = (size_t)(b * SEQ + kv1 + r) * 3072 + h * 64 + kc;
                CP16(smem_u32(Kd + r * KS_S + kc), qkv + base + 1024);
                CP16(smem_u32(Vd + r * VS_S + kc), qkv + base + 2048);
            }
        }
        CP_COMMIT();
        CP_WAIT1();
        __syncthreads();

        const float* Kc = Ks + (t & 1) * 64 * KS_S;
        const float* Vc = Vs + (t & 1) * 64 * VS_S;

        // ---- S = Qs @ K^T ----
        float s[4][4];
        #pragma unroll
        for (int nf = 0; nf < 4; nf++)
            #pragma unroll
            for (int i = 0; i < 4; i++) s[nf][i] = 0.f;

        #pragma unroll
        for (int ks = 0; ks < 8; ks++) {
            const int k = ks * 8;
            const int r0 = wq * 16 + g2;
            uint32_t a0 = fbits(Qs[r0 * QS_S + k + t4]);
            uint32_t a1 = fbits(Qs[(r0 + 8) * QS_S + k + t4]);
            uint32_t a2 = fbits(Qs[r0 * QS_S + k + 4 + t4]);
            uint32_t a3 = fbits(Qs[(r0 + 8) * QS_S + k + 4 + t4]);
            #pragma unroll
            for (int nf = 0; nf < 4; nf++) {
                int cc = wh * 32 + nf * 8 + g2;
                uint32_t b0 = fbits(Kc[cc * KS_S + k + t4]);
                uint32_t b1 = fbits(Kc[cc * KS_S + k + 4 + t4]);
                mma8(s[nf], a0, a1, a2, a3, b0, b1);
            }
        }
        #pragma unroll
        for (int nf = 0; nf < 4; nf++) {
            int cc = wh * 32 + nf * 8 + t4 * 2;
            int r0 = wq * 16 + g2;
            *reinterpret_cast<float2*>(&Ss[r0 * SS_S + cc])       = make_float2(s[nf][0], s[nf][1]);
            *reinterpret_cast<float2*>(&Ss[(r0 + 8) * SS_S + cc]) = make_float2(s[nf][2], s[nf][3]);
        }
        __syncthreads();

        // ---- online softmax ----
        const bool need_mask = (t == qb);
        float sv[16];
        float tmax = -1e30f;
        #pragma unroll
        for (int jj = 0; jj < 16; jj++) {
            int j = sg + jj * 4;
            float x = Ss[sr * SS_S + j];
            if (need_mask && (t * BKV + j > rg)) x = -1e30f;
            sv[jj] = x;
            tmax = fmaxf(tmax, x);
        }
        tmax = fmaxf(tmax, __shfl_xor_sync(0xffffffffu, tmax, 1));
        tmax = fmaxf(tmax, __shfl_xor_sync(0xffffffffu, tmax, 2));
        const float m_new = fmaxf(m, tmax);
        const float alpha = __expf(m - m_new);
        float psum = 0.f;
        #pragma unroll
        for (int jj = 0; jj < 16; jj++) {
            float p = __expf(sv[jj] - m_new);
            Ss[sr * SS_S + sg + jj * 4] = tf32f(p);
            psum += p;
        }
        psum += __shfl_xor_sync(0xffffffffu, psum, 1);
        psum += __shfl_xor_sync(0xffffffffu, psum, 2);
        l = l * alpha + psum;
        m = m_new;
        if (sg == 0) alphas[sr] = alpha;
        __syncthreads();

        // ---- O = alpha*O + P @ V ----
        const float av0 = alphas[wq * 16 + g2];
        const float av1 = alphas[wq * 16 + 8 + g2];
        #pragma unroll
        for (int nf = 0; nf < 4; nf++) {
            o[nf][0] *= av0; o[nf][1] *= av0;
            o[nf][2] *= av1; o[nf][3] *= av1;
        }
        #pragma unroll
        for (int ks = 0; ks < 8; ks++) {
            const int k = ks * 8;
            const int r0 = wq * 16 + g2;
            uint32_t a0 = fbits(Ss[r0 * SS_S + k + t4]);
            uint32_t a1 = fbits(Ss[(r0 + 8) * SS_S + k + t4]);
            uint32_t a2 = fbits(Ss[r0 * SS_S + k + 4 + t4]);
            uint32_t a3 = fbits(Ss[(r0 + 8) * SS_S + k + 4 + t4]);
            #pragma unroll
            for (int nf = 0; nf < 4; nf++) {
                int cc = wh * 32 + nf * 8 + g2;
                uint32_t b0 = fbits(Vc[(k + t4) * VS_S + cc]);
                uint32_t b1 = fbits(Vc[(k + 4 + t4) * VS_S + cc]);
                mma8(o[nf], a0, a1, a2, a3, b0, b1);
            }
        }
        __syncthreads();   // protect Ss/Vs before next iter's cp.async / S-store
    }

    if (sg == 0) linv[sr] = 1.0f / l;
    __syncthreads();

    const float li0 = linv[wq * 16 + g2];
    const float li1 = linv[wq * 16 + 8 + g2];
    #pragma unroll
    for (int nf = 0; nf < 4; nf++) {
        int cc = wh * 32 + nf * 8 + t4 * 2;
        int r0 = wq * 16 + g2;
        float* p0 = attn_out + (size_t)(b * SEQ + q0 + r0) * HID + h * 64 + cc;
        float* p1 = attn_out + (size_t)(b * SEQ + q0 + r0 + 8) * HID + h * 64 + cc;
        *reinterpret_cast<float2*>(p0) =
            make_float2(tf32f(o[nf][0] * li0), tf32f(o[nf][1] * li0));
        *reinterpret_cast<float2*>(p1) =
            make_float2(tf32f(o[nf][2] * li1), tf32f(o[nf][3] * li1));
    }
}

// ---------------------------------------------------------------------------
extern "C" void kernel_launch(void* const* d_in, const int* in_sizes, int n_in,
                              void* d_out, int out_size)
{
    const float* x     = (const float*)d_in[0];
    const float* w_qkv = (const float*)d_in[1];
    const float* b_qkv = (const float*)d_in[2];
    const float* w_out = (const float*)d_in[3];
    const float* b_out = (const float*)d_in[4];
    float* out = (float*)d_out;

    float *qkv, *attn, *xc, *w1, *w2;
    cudaGetSymbolAddress((void**)&qkv,  g_qkv);
    cudaGetSymbolAddress((void**)&attn, g_attn);
    cudaGetSymbolAddress((void**)&xc,   g_xc);
    cudaGetSymbolAddress((void**)&w1,   g_w1);
    cudaGetSymbolAddress((void**)&w2,   g_w2);

    cudaFuncSetAttribute(gemm_tf32,  cudaFuncAttributeMaxDynamicSharedMemorySize, GEMM_SMEM);
    cudaFuncSetAttribute(flash_tf32, cudaFuncAttributeMaxDynamicSharedMemorySize, FLASH_SMEM);

    // 0) round inputs to tf32
    round_tf32_kernel<<<(NTOK * HID / 4 + 255) / 256, 256>>>(x, xc, NTOK * HID / 4);
    round_tf32_kernel<<<(HID * 3 * HID / 4 + 255) / 256, 256>>>(w_qkv, w1, HID * 3 * HID / 4);
    round_tf32_kernel<<<(HID * HID / 4 + 255) / 256, 256>>>(w_out, w2, HID * HID / 4);

    // 1) qkv = xc @ w1 + b_qkv (output rounded to tf32)
    dim3 g1(3 * HID / 128, NTOK / 128);
    gemm_tf32<<<g1, 256, GEMM_SMEM>>>(xc, w1, b_qkv, qkv, NTOK, 3 * HID, HID, 1);

    // 2) causal flash attention (output rounded to tf32)
    dim3 g2(SEQ / BQ, NHEAD, BATCH);
    flash_tf32<<<g2, 256, FLASH_SMEM>>>(qkv, attn);

    // 3) out = attn @ w2 + b_out (full fp32 out)
    dim3 g3(HID / 128, NTOK / 128);
    gemm_tf32<<<g3, 256, GEMM_SMEM>>>(attn, w2, b_out, out, NTOK, HID, HID, 0);
}

// round 7
// speedup vs baseline: 5.8314x; 1.0316x over previous
#include <cuda_runtime.h>
#include <cstdint>

#define BATCH 2
#define SEQ   2048
#define HID   1024
#define NHEAD 16
#define HDIM  64
#define NTOK  (BATCH*SEQ)

// Scratch (device globals: allocation-free rule)
__device__ float g_qkv[NTOK * 3 * HID];   // (B,S,3,NH,HD) tf32-rounded
__device__ float g_attn[NTOK * HID];      // tf32-rounded
__device__ float g_xc[NTOK * HID];
__device__ float g_w1[HID * 3 * HID];
__device__ float g_w2[HID * HID];

// ---------------------------------------------------------------------------
__device__ __forceinline__ float tf32f(float x) {
    uint32_t u;
    asm("cvt.rna.tf32.f32 %0, %1;" : "=r"(u) : "f"(x));
    return __uint_as_float(u);
}
__device__ __forceinline__ float ex2(float x) {
    float y;
    asm("ex2.approx.ftz.f32 %0, %1;" : "=f"(y) : "f"(x));
    return y;
}
__device__ __forceinline__ uint32_t fbits(float x) { return __float_as_uint(x); }
__device__ __forceinline__ uint32_t smem_u32(const void* p) {
    return (uint32_t)__cvta_generic_to_shared(p);
}
#define CP16(dst_u32, src_ptr) \
    asm volatile("cp.async.ca.shared.global [%0], [%1], 16;" :: "r"(dst_u32), "l"(src_ptr))
#define CP_COMMIT() asm volatile("cp.async.commit_group;")
#define CP_WAIT1()  asm volatile("cp.async.wait_group 1;")
#define CP_WAIT0()  asm volatile("cp.async.wait_group 0;")

__device__ __forceinline__ void mma8(float* c,
                                     uint32_t a0, uint32_t a1, uint32_t a2, uint32_t a3,
                                     uint32_t b0, uint32_t b1) {
    asm volatile(
        "mma.sync.aligned.m16n8k8.row.col.f32.tf32.tf32.f32 "
        "{%0,%1,%2,%3}, {%4,%5,%6,%7}, {%8,%9}, {%0,%1,%2,%3};"
        : "+f"(c[0]), "+f"(c[1]), "+f"(c[2]), "+f"(c[3])
        : "r"(a0), "r"(a1), "r"(a2), "r"(a3), "r"(b0), "r"(b1));
}

// ---------------------------------------------------------------------------
// tf32 rounding prepass
// ---------------------------------------------------------------------------
__global__ void round_tf32_kernel(const float* __restrict__ in,
                                  float* __restrict__ out, int n4)
{
    int i = blockIdx.x * blockDim.x + threadIdx.x;
    if (i < n4) {
        float4 v = reinterpret_cast<const float4*>(in)[i];
        reinterpret_cast<float4*>(out)[i] =
            make_float4(tf32f(v.x), tf32f(v.y), tf32f(v.z), tf32f(v.w));
    }
}

// ---------------------------------------------------------------------------
// TF32 GEMM: 128x128x32 CTA tile, 4 warps (2x2), 64x64 warp tile,
// cp.async 2-stage. Inputs pre-rounded to tf32.
// ---------------------------------------------------------------------------
#define GA 36
#define GB 132
#define GEMM_SMEM ((2*128*GA + 2*32*GB) * 4)   // 70656 B

__global__ __launch_bounds__(128) void gemm_tf32(
    const float* __restrict__ A, const float* __restrict__ B,
    const float* __restrict__ bias, float* __restrict__ C,
    int M, int N, int K, int round_out)
{
    extern __shared__ float sm[];
    float* As = sm;                 // [2][128][36]
    float* Bs = sm + 2 * 128 * GA;  // [2][32][132]

    const int tid  = threadIdx.x;
    const int warp = tid >> 5, lane = tid & 31;
    const int wm = warp >> 1, wn = warp & 1;   // 2 x 2 warp grid
    const int g2 = lane >> 2, t4 = lane & 3;
    const int cRow = blockIdx.y, cCol = blockIdx.x;

    const float* Ab = A + (size_t)cRow * 128 * K;
    const float* Bb = B + cCol * 128;

    float c[4][8][4];
    #pragma unroll
    for (int mf = 0; mf < 4; mf++)
        #pragma unroll
        for (int nf = 0; nf < 8; nf++)
            #pragma unroll
            for (int i = 0; i < 4; i++) c[mf][nf][i] = 0.f;

    const int nk = K >> 5;

    // prefetch stage 0
    {
        #pragma unroll
        for (int i = 0; i < 8; i++) {
            int idx = tid + i * 128;
            int r = idx >> 3, c4 = (idx & 7) << 2;
            CP16(smem_u32(As + r * GA + c4), Ab + (size_t)r * K + c4);
        }
        #pragma unroll
        for (int i = 0; i < 8; i++) {
            int idx = tid + i * 128;
            int r = idx >> 5, c4 = (idx & 31) << 2;
            CP16(smem_u32(Bs + r * GB + c4), Bb + (size_t)r * N + c4);
        }
        CP_COMMIT();
    }

    for (int it = 0; it < nk; it++) {
        if (it + 1 < nk) {
            const int k0 = (it + 1) << 5;
            float* Ad = As + ((it + 1) & 1) * 128 * GA;
            float* Bd = Bs + ((it + 1) & 1) * 32 * GB;
            #pragma unroll
            for (int i = 0; i < 8; i++) {
                int idx = tid + i * 128;
                int r = idx >> 3, c4 = (idx & 7) << 2;
                CP16(smem_u32(Ad + r * GA + c4), Ab + (size_t)r * K + k0 + c4);
            }
            #pragma unroll
            for (int i = 0; i < 8; i++) {
                int idx = tid + i * 128;
                int r = idx >> 5, c4 = (idx & 31) << 2;
                CP16(smem_u32(Bd + r * GB + c4), Bb + (size_t)(k0 + r) * N + c4);
            }
        }
        CP_COMMIT();
        CP_WAIT1();
        __syncthreads();

        const float* Ac = As + (it & 1) * 128 * GA;
        const float* Bc = Bs + (it & 1) * 32 * GB;

        #pragma unroll
        for (int ks = 0; ks < 4; ks++) {
            const int k = ks * 8;
            uint32_t a[4][4], b[8][2];
            #pragma unroll
            for (int mf = 0; mf < 4; mf++) {
                int r0 = wm * 64 + mf * 16 + g2;
                a[mf][0] = fbits(Ac[r0 * GA + k + t4]);
                a[mf][1] = fbits(Ac[(r0 + 8) * GA + k + t4]);
                a[mf][2] = fbits(Ac[r0 * GA + k + 4 + t4]);
                a[mf][3] = fbits(Ac[(r0 + 8) * GA + k + 4 + t4]);
            }
            #pragma unroll
            for (int nf = 0; nf < 8; nf++) {
                int cc = wn * 64 + nf * 8 + g2;
                b[nf][0] = fbits(Bc[(k + t4) * GB + cc]);
                b[nf][1] = fbits(Bc[(k + 4 + t4) * GB + cc]);
            }
            #pragma unroll
            for (int mf = 0; mf < 4; mf++)
                #pragma unroll
                for (int nf = 0; nf < 8; nf++)
                    mma8(c[mf][nf], a[mf][0], a[mf][1], a[mf][2], a[mf][3],
                         b[nf][0], b[nf][1]);
        }
        __syncthreads();
    }

    #pragma unroll
    for (int nf = 0; nf < 8; nf++) {
        int cc = cCol * 128 + wn * 64 + nf * 8 + t4 * 2;
        float b0 = bias[cc], b1 = bias[cc + 1];
        #pragma unroll
        for (int mf = 0; mf < 4; mf++) {
            int r0 = cRow * 128 + wm * 64 + mf * 16 + g2;
            float v00 = c[mf][nf][0] + b0, v01 = c[mf][nf][1] + b1;
            float v10 = c[mf][nf][2] + b0, v11 = c[mf][nf][3] + b1;
            if (round_out) {
                v00 = tf32f(v00); v01 = tf32f(v01);
                v10 = tf32f(v10); v11 = tf32f(v11);
            }
            *reinterpret_cast<float2*>(C + (size_t)r0 * N + cc)       = make_float2(v00, v01);
            *reinterpret_cast<float2*>(C + (size_t)(r0 + 8) * N + cc) = make_float2(v10, v11);
        }
    }
}

// ---------------------------------------------------------------------------
// TF32 causal flash attention, register softmax. BQ=64, BKV=64, 256 threads.
// Pipeline order: wait tile t -> barrier -> THEN prefetch t+1 (race-free).
// ---------------------------------------------------------------------------
#define BQ  64
#define BKV 64
#define QS_S 68
#define KS_S 68
#define VS_S 72
#define SS_S 68
#define SCALE_L2E 0.18033688011112042f   // 0.125 * log2(e)
#define FLASH_SMEM ((64*QS_S + 2*64*KS_S + 2*64*VS_S + 64*SS_S + 256) * 4)

__global__ __launch_bounds__(256, 2) void flash_tf32(
    const float* __restrict__ qkv, float* __restrict__ attn_out)
{
    extern __shared__ float sm[];
    float* Qs   = sm;                     // [64][68]
    float* Ks   = Qs + 64 * QS_S;         // [2][64][68]
    float* Vs   = Ks + 2 * 64 * KS_S;     // [2][64][72]
    float* Ps   = Vs + 2 * 64 * VS_S;     // [64][68]
    float* pmax = Ps + 64 * SS_S;         // [2][64]
    float* psum = pmax + 128;             // [2][64]

    const int qb = gridDim.x - 1 - blockIdx.x;   // heavy blocks first
    const int h = blockIdx.y, b = blockIdx.z;
    const int tid = threadIdx.x, warp = tid >> 5, lane = tid & 31;
    const int g2 = lane >> 2, t4 = lane & 3;
    const int q0 = qb * BQ;
    const int wq = warp >> 1, wh = warp & 1;
    const int kr = tid >> 4, kc = (tid & 15) << 2;

    // Q tile: scale by 0.125*log2e, round to tf32
    #pragma unroll
    for (int i = 0; i < 4; i++) {
        int idx = tid + i * 256;
        int r = idx >> 4, c4 = (idx & 15) << 2;
        float4 v = *reinterpret_cast<const float4*>(
            qkv + (size_t)(b * SEQ + q0 + r) * 3072 + h * 64 + c4);
        Qs[r * QS_S + c4 + 0] = tf32f(v.x * SCALE_L2E);
        Qs[r * QS_S + c4 + 1] = tf32f(v.y * SCALE_L2E);
        Qs[r * QS_S + c4 + 2] = tf32f(v.z * SCALE_L2E);
        Qs[r * QS_S + c4 + 3] = tf32f(v.w * SCALE_L2E);
    }

    const int r0l = wq * 16 + g2;           // local rows r0l, r0l+8
    const int grow0 = q0 + r0l, grow1 = grow0 + 8;
    float m0 = -1e30f, m1 = -1e30f, l0 = 0.f, l1 = 0.f;
    float o[4][4];
    #pragma unroll
    for (int nf = 0; nf < 4; nf++)
        #pragma unroll
        for (int i = 0; i < 4; i++) o[nf][i] = 0.f;

    const int nkv = qb + 1;

    // prefetch KV tile 0 (stage 0)
    #pragma unroll
    for (int i = 0; i < 4; i++) {
        int r = kr + i * 16;
        size_t base = (size_t)(b * SEQ + r) * 3072 + h * 64 + kc;
        CP16(smem_u32(Ks + r * KS_S + kc), qkv + base + 1024);
        CP16(smem_u32(Vs + r * VS_S + kc), qkv + base + 2048);
    }
    CP_COMMIT();

    for (int t = 0; t < nkv; t++) {
        // tile t is the only pending group -> wait_group 0 == tile t ready.
        CP_WAIT0();
        __syncthreads();                                  // (a) also fences prev PV

        // NOW safe to overwrite the other stage: prefetch t+1
        if (t + 1 < nkv) {
            const int kv1 = (t + 1) * BKV;
            float* Kd = Ks + ((t + 1) & 1) * 64 * KS_S;
            float* Vd = Vs + ((t + 1) & 1) * 64 * VS_S;
            #pragma unroll
            for (int i = 0; i < 4; i++) {
                int r = kr + i * 16;
                size_t base = (size_t)(b * SEQ + kv1 + r) * 3072 + h * 64 + kc;
                CP16(smem_u32(Kd + r * KS_S + kc), qkv + base + 1024);
                CP16(smem_u32(Vd + r * VS_S + kc), qkv + base + 2048);
            }
            CP_COMMIT();
        }

        const float* Kc = Ks + (t & 1) * 64 * KS_S;
        const float* Vc = Vs + (t & 1) * 64 * VS_S;

        // ---- S = Qs @ K^T  (units: log2) ----
        float s[4][4];
        #pragma unroll
        for (int nf = 0; nf < 4; nf++)
            #pragma unroll
            for (int i = 0; i < 4; i++) s[nf][i] = 0.f;

        #pragma unroll
        for (int ks = 0; ks < 8; ks++) {
            const int k = ks * 8;
            uint32_t a0 = fbits(Qs[r0l * QS_S + k + t4]);
            uint32_t a1 = fbits(Qs[(r0l + 8) * QS_S + k + t4]);
            uint32_t a2 = fbits(Qs[r0l * QS_S + k + 4 + t4]);
            uint32_t a3 = fbits(Qs[(r0l + 8) * QS_S + k + 4 + t4]);
            #pragma unroll
            for (int nf = 0; nf < 4; nf++) {
                int cc = wh * 32 + nf * 8 + g2;
                uint32_t b0 = fbits(Kc[cc * KS_S + k + t4]);
                uint32_t b1 = fbits(Kc[cc * KS_S + k + 4 + t4]);
                mma8(s[nf], a0, a1, a2, a3, b0, b1);
            }
        }

        // ---- mask + warp-local row max ----
        const bool nm = (t == qb);
        float pv0[8], pv1[8];
        float mx0 = -1e30f, mx1 = -1e30f;
        #pragma unroll
        for (int nf = 0; nf < 4; nf++) {
            #pragma unroll
            for (int j = 0; j < 2; j++) {
                int gc = t * BKV + wh * 32 + nf * 8 + t4 * 2 + j;
                float x0 = s[nf][j];
                float x1 = s[nf][2 + j];
                if (nm && gc > grow0) x0 = -1e30f;
                if (nm && gc > grow1) x1 = -1e30f;
                pv0[nf * 2 + j] = x0; pv1[nf * 2 + j] = x1;
                mx0 = fmaxf(mx0, x0); mx1 = fmaxf(mx1, x1);
            }
        }
        mx0 = fmaxf(mx0, __shfl_xor_sync(0xffffffffu, mx0, 1));
        mx0 = fmaxf(mx0, __shfl_xor_sync(0xffffffffu, mx0, 2));
        mx1 = fmaxf(mx1, __shfl_xor_sync(0xffffffffu, mx1, 1));
        mx1 = fmaxf(mx1, __shfl_xor_sync(0xffffffffu, mx1, 2));
        if (t4 == 0) {
            pmax[wh * 64 + r0l]     = mx0;
            pmax[wh * 64 + r0l + 8] = mx1;
        }
        __syncthreads();                                  // (b)

        const float mn0 = fmaxf(m0, fmaxf(mx0, pmax[(1 - wh) * 64 + r0l]));
        const float mn1 = fmaxf(m1, fmaxf(mx1, pmax[(1 - wh) * 64 + r0l + 8]));
        const float a0s = ex2(m0 - mn0);
        const float a1s = ex2(m1 - mn1);

        float ps0 = 0.f, ps1 = 0.f;
        #pragma unroll
        for (int nf = 0; nf < 4; nf++) {
            float p00 = ex2(pv0[nf * 2]     - mn0);
            float p01 = ex2(pv0[nf * 2 + 1] - mn0);
            float p10 = ex2(pv1[nf * 2]     - mn1);
            float p11 = ex2(pv1[nf * 2 + 1] - mn1);
            ps0 += p00 + p01; ps1 += p10 + p11;
            int cc = wh * 32 + nf * 8 + t4 * 2;
            *reinterpret_cast<float2*>(&Ps[r0l * SS_S + cc]) =
                make_float2(tf32f(p00), tf32f(p01));
            *reinterpret_cast<float2*>(&Ps[(r0l + 8) * SS_S + cc]) =
                make_float2(tf32f(p10), tf32f(p11));
        }
        ps0 += __shfl_xor_sync(0xffffffffu, ps0, 1);
        ps0 += __shfl_xor_sync(0xffffffffu, ps0, 2);
        ps1 += __shfl_xor_sync(0xffffffffu, ps1, 1);
        ps1 += __shfl_xor_sync(0xffffffffu, ps1, 2);
        if (t4 == 0) {
            psum[wh * 64 + r0l]     = ps0;
            psum[wh * 64 + r0l + 8] = ps1;
        }
        // rescale O while waiting
        #pragma unroll
        for (int nf = 0; nf < 4; nf++) {
            o[nf][0] *= a0s; o[nf][1] *= a0s;
            o[nf][2] *= a1s; o[nf][3] *= a1s;
        }
        __syncthreads();                                  // (c)

        l0 = l0 * a0s + ps0 + psum[(1 - wh) * 64 + r0l];
        l1 = l1 * a1s + ps1 + psum[(1 - wh) * 64 + r0l + 8];
        m0 = mn0; m1 = mn1;

        // ---- O += P @ V ----
        #pragma unroll
        for (int ks = 0; ks < 8; ks++) {
            const int k = ks * 8;
            uint32_t a0 = fbits(Ps[r0l * SS_S + k + t4]);
            uint32_t a1 = fbits(Ps[(r0l + 8) * SS_S + k + t4]);
            uint32_t a2 = fbits(Ps[r0l * SS_S + k + 4 + t4]);
            uint32_t a3 = fbits(Ps[(r0l + 8) * SS_S + k + 4 + t4]);
            #pragma unroll
            for (int nf = 0; nf < 4; nf++) {
                int cc = wh * 32 + nf * 8 + g2;
                uint32_t b0 = fbits(Vc[(k + t4) * VS_S + cc]);
                uint32_t b1 = fbits(Vc[(k + 4 + t4) * VS_S + cc]);
                mma8(o[nf], a0, a1, a2, a3, b0, b1);
            }
        }
    }

    const float inv0 = 1.f / l0, inv1 = 1.f / l1;
    #pragma unroll
    for (int nf = 0; nf < 4; nf++) {
        int cc = wh * 32 + nf * 8 + t4 * 2;
        float* p0 = attn_out + (size_t)(b * SEQ + grow0) * HID + h * 64 + cc;
        float* p1 = attn_out + (size_t)(b * SEQ + grow1) * HID + h * 64 + cc;
        *reinterpret_cast<float2*>(p0) =
            make_float2(tf32f(o[nf][0] * inv0), tf32f(o[nf][1] * inv0));
        *reinterpret_cast<float2*>(p1) =
            make_float2(tf32f(o[nf][2] * inv1), tf32f(o[nf][3] * inv1));
    }
}

// ---------------------------------------------------------------------------
extern "C" void kernel_launch(void* const* d_in, const int* in_sizes, int n_in,
                              void* d_out, int out_size)
{
    const float* x     = (const float*)d_in[0];
    const float* w_qkv = (const float*)d_in[1];
    const float* b_qkv = (const float*)d_in[2];
    const float* w_out = (const float*)d_in[3];
    const float* b_out = (const float*)d_in[4];
    float* out = (float*)d_out;

    float *qkv, *attn, *xc, *w1, *w2;
    cudaGetSymbolAddress((void**)&qkv,  g_qkv);
    cudaGetSymbolAddress((void**)&attn, g_attn);
    cudaGetSymbolAddress((void**)&xc,   g_xc);
    cudaGetSymbolAddress((void**)&w1,   g_w1);
    cudaGetSymbolAddress((void**)&w2,   g_w2);

    cudaFuncSetAttribute(gemm_tf32,  cudaFuncAttributeMaxDynamicSharedMemorySize, GEMM_SMEM);
    cudaFuncSetAttribute(flash_tf32, cudaFuncAttributeMaxDynamicSharedMemorySize, FLASH_SMEM);

    // 0) round inputs to tf32
    round_tf32_kernel<<<(NTOK * HID / 4 + 255) / 256, 256>>>(x, xc, NTOK * HID / 4);
    round_tf32_kernel<<<(HID * 3 * HID / 4 + 255) / 256, 256>>>(w_qkv, w1, HID * 3 * HID / 4);
    round_tf32_kernel<<<(HID * HID / 4 + 255) / 256, 256>>>(w_out, w2, HID * HID / 4);

    // 1) qkv = xc @ w1 + b_qkv (output rounded to tf32)
    dim3 g1(3 * HID / 128, NTOK / 128);
    gemm_tf32<<<g1, 128, GEMM_SMEM>>>(xc, w1, b_qkv, qkv, NTOK, 3 * HID, HID, 1);

    // 2) causal flash attention
    dim3 g2(SEQ / BQ, NHEAD, BATCH);
    flash_tf32<<<g2, 256, FLASH_SMEM>>>(qkv, attn);

    // 3) out = attn @ w2 + b_out
    dim3 g3(HID / 128, NTOK / 128);
    gemm_tf32<<<g3, 128, GEMM_SMEM>>>(attn, w2, b_out, out, NTOK, HID, HID, 0);
}